// round 1
// baseline (speedup 1.0000x reference)
#include <cuda_runtime.h>

// TimeSeriesLSTMRegressor: 2-layer LSTM (IN=16, H=32, T=512, B=4096) + MLP head.
// One warp per sequence, one lane per hidden unit. Weights in dynamic smem,
// packed float4 across the 4 gates (i,f,g,o). Fully fused: both LSTM layers +
// head in a single persistent kernel; no intermediate global traffic.

#define FULLMASK 0xffffffffu

constexpr int T_LEN = 512;
constexpr int IN_DIM = 16;
constexpr int H_DIM = 32;
constexpr int WARPS_PER_BLOCK = 8;
constexpr int THREADS = WARPS_PER_BLOCK * 32;

struct SmemW {
    float4 wih0[IN_DIM][H_DIM];  // [k][u] -> gates (i,f,g,o) of unit u, input k
    float4 whh0[H_DIM][H_DIM];   // [j][u]
    float4 wih1[H_DIM][H_DIM];   // [j][u]
    float4 whh1[H_DIM][H_DIM];   // [j][u]
    float4 bg0[H_DIM];           // bih0+bhh0 packed per gate
    float4 bg1[H_DIM];           // bih1+bhh1
};

__device__ __forceinline__ float fast_sigmoid(float x) {
    // 1/(1+e^-x): e^-x in [0, inf); fdividef(1, inf) = 0, so safe at extremes.
    return __fdividef(1.0f, 1.0f + __expf(-x));
}

__device__ __forceinline__ float fast_tanh(float x) {
    // tanh(|x|) = (1-e)/(1+e), e = exp(-2|x|) in (0,1]; sign restored after.
    float a = fabsf(x);
    float e = __expf(-2.0f * a);
    float r = __fdividef(1.0f - e, 1.0f + e);
    return copysignf(r, x);
}

__global__ void __launch_bounds__(THREADS)
lstm_fused_kernel(const float* __restrict__ x,
                  const float* __restrict__ Wih0, const float* __restrict__ Whh0,
                  const float* __restrict__ bih0, const float* __restrict__ bhh0,
                  const float* __restrict__ Wih1, const float* __restrict__ Whh1,
                  const float* __restrict__ bih1, const float* __restrict__ bhh1,
                  const float* __restrict__ W1, const float* __restrict__ b1,
                  const float* __restrict__ W2, const float* __restrict__ b2,
                  float* __restrict__ out, int batch) {
    extern __shared__ char smem_raw[];
    SmemW* s = reinterpret_cast<SmemW*>(smem_raw);

    const int tid = threadIdx.x;

    // ---- Stage weights into smem, gate-packed as float4 ----
    for (int i = tid; i < IN_DIM * H_DIM; i += THREADS) {
        int k = i / H_DIM, u = i % H_DIM;
        s->wih0[k][u] = make_float4(Wih0[(0 * H_DIM + u) * IN_DIM + k],
                                    Wih0[(1 * H_DIM + u) * IN_DIM + k],
                                    Wih0[(2 * H_DIM + u) * IN_DIM + k],
                                    Wih0[(3 * H_DIM + u) * IN_DIM + k]);
    }
    for (int i = tid; i < H_DIM * H_DIM; i += THREADS) {
        int j = i / H_DIM, u = i % H_DIM;
        s->whh0[j][u] = make_float4(Whh0[(0 * H_DIM + u) * H_DIM + j],
                                    Whh0[(1 * H_DIM + u) * H_DIM + j],
                                    Whh0[(2 * H_DIM + u) * H_DIM + j],
                                    Whh0[(3 * H_DIM + u) * H_DIM + j]);
        s->wih1[j][u] = make_float4(Wih1[(0 * H_DIM + u) * H_DIM + j],
                                    Wih1[(1 * H_DIM + u) * H_DIM + j],
                                    Wih1[(2 * H_DIM + u) * H_DIM + j],
                                    Wih1[(3 * H_DIM + u) * H_DIM + j]);
        s->whh1[j][u] = make_float4(Whh1[(0 * H_DIM + u) * H_DIM + j],
                                    Whh1[(1 * H_DIM + u) * H_DIM + j],
                                    Whh1[(2 * H_DIM + u) * H_DIM + j],
                                    Whh1[(3 * H_DIM + u) * H_DIM + j]);
    }
    for (int u = tid; u < H_DIM; u += THREADS) {
        s->bg0[u] = make_float4(bih0[0 * H_DIM + u] + bhh0[0 * H_DIM + u],
                                bih0[1 * H_DIM + u] + bhh0[1 * H_DIM + u],
                                bih0[2 * H_DIM + u] + bhh0[2 * H_DIM + u],
                                bih0[3 * H_DIM + u] + bhh0[3 * H_DIM + u]);
        s->bg1[u] = make_float4(bih1[0 * H_DIM + u] + bhh1[0 * H_DIM + u],
                                bih1[1 * H_DIM + u] + bhh1[1 * H_DIM + u],
                                bih1[2 * H_DIM + u] + bhh1[2 * H_DIM + u],
                                bih1[3 * H_DIM + u] + bhh1[3 * H_DIM + u]);
    }
    __syncthreads();

    const int warp = tid >> 5;
    const int lane = tid & 31;
    const int b = blockIdx.x * WARPS_PER_BLOCK + warp;
    if (b >= batch) return;

    const float* xb = x + (size_t)b * T_LEN * IN_DIM;

    float h0 = 0.f, c0 = 0.f, h1 = 0.f, c1 = 0.f;

    // Preload x[t=0] (lanes 0..15 hold the 16 inputs)
    float xv = (lane < IN_DIM) ? __ldg(xb + lane) : 0.f;

    for (int t = 0; t < T_LEN; t++) {
        // Prefetch next timestep's x while we compute this one.
        float xnext = 0.f;
        if (t + 1 < T_LEN && lane < IN_DIM)
            xnext = __ldg(xb + (t + 1) * IN_DIM + lane);

        // ---- Layer 0 ----
        float4 a = s->bg0[lane];
#pragma unroll
        for (int k = 0; k < IN_DIM; k++) {
            float xk = __shfl_sync(FULLMASK, xv, k);
            float4 w = s->wih0[k][lane];
            a.x = fmaf(w.x, xk, a.x);
            a.y = fmaf(w.y, xk, a.y);
            a.z = fmaf(w.z, xk, a.z);
            a.w = fmaf(w.w, xk, a.w);
        }
#pragma unroll
        for (int j = 0; j < H_DIM; j++) {
            float hj = __shfl_sync(FULLMASK, h0, j);
            float4 w = s->whh0[j][lane];
            a.x = fmaf(w.x, hj, a.x);
            a.y = fmaf(w.y, hj, a.y);
            a.z = fmaf(w.z, hj, a.z);
            a.w = fmaf(w.w, hj, a.w);
        }
        {
            float ig = fast_sigmoid(a.x);
            float fg = fast_sigmoid(a.y);
            float gg = fast_tanh(a.z);
            float og = fast_sigmoid(a.w);
            c0 = fmaf(fg, c0, ig * gg);
            h0 = og * fast_tanh(c0);
        }

        // ---- Layer 1 (input = h0 just produced) ----
        float4 a1 = s->bg1[lane];
#pragma unroll
        for (int j = 0; j < H_DIM; j++) {
            float hj = __shfl_sync(FULLMASK, h0, j);
            float4 w = s->wih1[j][lane];
            a1.x = fmaf(w.x, hj, a1.x);
            a1.y = fmaf(w.y, hj, a1.y);
            a1.z = fmaf(w.z, hj, a1.z);
            a1.w = fmaf(w.w, hj, a1.w);
        }
#pragma unroll
        for (int j = 0; j < H_DIM; j++) {
            float hj = __shfl_sync(FULLMASK, h1, j);
            float4 w = s->whh1[j][lane];
            a1.x = fmaf(w.x, hj, a1.x);
            a1.y = fmaf(w.y, hj, a1.y);
            a1.z = fmaf(w.z, hj, a1.z);
            a1.w = fmaf(w.w, hj, a1.w);
        }
        {
            float ig = fast_sigmoid(a1.x);
            float fg = fast_sigmoid(a1.y);
            float gg = fast_tanh(a1.z);
            float og = fast_sigmoid(a1.w);
            c1 = fmaf(fg, c1, ig * gg);
            h1 = og * fast_tanh(c1);
        }

        xv = xnext;
    }

    // ---- Head: z = relu(h1 @ W1.T + b1); y = z @ W2.T + b2 ----
    float z = 0.f;
#pragma unroll
    for (int j = 0; j < H_DIM; j++) {
        float hj = __shfl_sync(FULLMASK, h1, j);
        if (lane < 16) z = fmaf(__ldg(W1 + lane * H_DIM + j), hj, z);
    }
    float val = 0.f;
    if (lane < 16) {
        z += __ldg(b1 + lane);
        z = fmaxf(z, 0.f);
        val = z * __ldg(W2 + lane);
    }
#pragma unroll
    for (int off = 8; off >= 1; off >>= 1)
        val += __shfl_xor_sync(FULLMASK, val, off);
    if (lane == 0) out[b] = val + __ldg(b2);
}

extern "C" void kernel_launch(void* const* d_in, const int* in_sizes, int n_in,
                              void* d_out, int out_size) {
    const float* x    = (const float*)d_in[0];
    const float* Wih0 = (const float*)d_in[1];
    const float* Whh0 = (const float*)d_in[2];
    const float* bih0 = (const float*)d_in[3];
    const float* bhh0 = (const float*)d_in[4];
    const float* Wih1 = (const float*)d_in[5];
    const float* Whh1 = (const float*)d_in[6];
    const float* bih1 = (const float*)d_in[7];
    const float* bhh1 = (const float*)d_in[8];
    const float* W1   = (const float*)d_in[9];
    const float* b1   = (const float*)d_in[10];
    const float* W2   = (const float*)d_in[11];
    const float* b2   = (const float*)d_in[12];
    float* out = (float*)d_out;

    int batch = in_sizes[0] / (T_LEN * IN_DIM);  // 4096

    cudaFuncSetAttribute(lstm_fused_kernel,
                         cudaFuncAttributeMaxDynamicSharedMemorySize,
                         (int)sizeof(SmemW));

    int blocks = (batch + WARPS_PER_BLOCK - 1) / WARPS_PER_BLOCK;
    lstm_fused_kernel<<<blocks, THREADS, sizeof(SmemW)>>>(
        x, Wih0, Whh0, bih0, bhh0, Wih1, Whh1, bih1, bhh1,
        W1, b1, W2, b2, out, batch);
}

// round 2
// speedup vs baseline: 1.3351x; 1.3351x over previous
#include <cuda_runtime.h>

// 2-layer LSTM (IN=16, H=32, T=512, B=4096) + MLP head, fully fused.
// R2 layout: warp = 4 sequences (4 groups x 8 lanes). Lane i of a group owns
// hidden units {i, i+8, i+16, i+24} of its group's sequence.
//  - Weight LDS.128: 8 lanes read 128B contiguous, 4 groups broadcast the same
//    addresses -> 1 wavefront per LDS serving 4 sequences (was 4 wavefronts/1 seq).
//  - Gate math uses packed fma.rn.f32x2 ((i,f) and (g,o) pairs) -> half the FMA instrs.
//  - h/x broadcasts via width-8 segment shuffles (one shfl serves all 4 groups).

#define FULLMASK 0xffffffffu

constexpr int T_LEN = 512;
constexpr int IN_DIM = 16;
constexpr int H_DIM = 32;
constexpr int SEQ_PER_WARP = 4;
constexpr int WARPS_PER_BLOCK = 7;   // 147 blocks x 7 warps = 1029 warps >= 1024
constexpr int THREADS = WARPS_PER_BLOCK * 32;

struct SmemW {
    float4 wih0[IN_DIM][H_DIM];  // [row k][unit u] = gates (i,f,g,o)
    float4 whh0[H_DIM][H_DIM];
    float4 wih1[H_DIM][H_DIM];
    float4 whh1[H_DIM][H_DIM];
    float4 bg0[H_DIM];           // bih0+bhh0, gate-packed
    float4 bg1[H_DIM];
};

typedef unsigned long long u64;

__device__ __forceinline__ u64 fma2(u64 a, u64 b, u64 c) {
    u64 d;
    asm("fma.rn.f32x2 %0, %1, %2, %3;" : "=l"(d) : "l"(a), "l"(b), "l"(c));
    return d;
}
__device__ __forceinline__ u64 pack2(float v) {
    u64 r;
    asm("mov.b64 %0, {%1, %1};" : "=l"(r) : "f"(v));
    return r;
}
__device__ __forceinline__ float2 unpack2(u64 v) {
    float2 r;
    asm("mov.b64 {%0, %1}, %2;" : "=f"(r.x), "=f"(r.y) : "l"(v));
    return r;
}

__device__ __forceinline__ float fast_sigmoid(float x) {
    return __fdividef(1.0f, 1.0f + __expf(-x));
}
__device__ __forceinline__ float fast_tanh(float x) {
    float a = fabsf(x);
    float e = __expf(-2.0f * a);
    float r = __fdividef(1.0f - e, 1.0f + e);
    return copysignf(r, x);
}

// One LSTM cell update from packed gate pre-activations.
__device__ __forceinline__ void lstm_cell(u64 a_if, u64 a_go, float& h, float& c) {
    float2 if_ = unpack2(a_if);
    float2 go  = unpack2(a_go);
    float ig = fast_sigmoid(if_.x);
    float fg = fast_sigmoid(if_.y);
    float gg = fast_tanh(go.x);
    float og = fast_sigmoid(go.y);
    c = fmaf(fg, c, ig * gg);
    h = og * fast_tanh(c);
}

__global__ void __launch_bounds__(THREADS, 1)
lstm_fused_kernel(const float* __restrict__ x,
                  const float* __restrict__ Wih0, const float* __restrict__ Whh0,
                  const float* __restrict__ bih0, const float* __restrict__ bhh0,
                  const float* __restrict__ Wih1, const float* __restrict__ Whh1,
                  const float* __restrict__ bih1, const float* __restrict__ bhh1,
                  const float* __restrict__ W1, const float* __restrict__ b1,
                  const float* __restrict__ W2, const float* __restrict__ b2,
                  float* __restrict__ out, int batch) {
    extern __shared__ char smem_raw[];
    SmemW* s = reinterpret_cast<SmemW*>(smem_raw);

    const int tid = threadIdx.x;

    // ---- Stage weights: gate-packed float4 per (row, unit) ----
    for (int i = tid; i < IN_DIM * H_DIM; i += THREADS) {
        int k = i / H_DIM, u = i % H_DIM;
        s->wih0[k][u] = make_float4(Wih0[(0 * H_DIM + u) * IN_DIM + k],
                                    Wih0[(1 * H_DIM + u) * IN_DIM + k],
                                    Wih0[(2 * H_DIM + u) * IN_DIM + k],
                                    Wih0[(3 * H_DIM + u) * IN_DIM + k]);
    }
    for (int i = tid; i < H_DIM * H_DIM; i += THREADS) {
        int j = i / H_DIM, u = i % H_DIM;
        s->whh0[j][u] = make_float4(Whh0[(0 * H_DIM + u) * H_DIM + j],
                                    Whh0[(1 * H_DIM + u) * H_DIM + j],
                                    Whh0[(2 * H_DIM + u) * H_DIM + j],
                                    Whh0[(3 * H_DIM + u) * H_DIM + j]);
        s->wih1[j][u] = make_float4(Wih1[(0 * H_DIM + u) * H_DIM + j],
                                    Wih1[(1 * H_DIM + u) * H_DIM + j],
                                    Wih1[(2 * H_DIM + u) * H_DIM + j],
                                    Wih1[(3 * H_DIM + u) * H_DIM + j]);
        s->whh1[j][u] = make_float4(Whh1[(0 * H_DIM + u) * H_DIM + j],
                                    Whh1[(1 * H_DIM + u) * H_DIM + j],
                                    Whh1[(2 * H_DIM + u) * H_DIM + j],
                                    Whh1[(3 * H_DIM + u) * H_DIM + j]);
    }
    for (int u = tid; u < H_DIM; u += THREADS) {
        s->bg0[u] = make_float4(bih0[0 * H_DIM + u] + bhh0[0 * H_DIM + u],
                                bih0[1 * H_DIM + u] + bhh0[1 * H_DIM + u],
                                bih0[2 * H_DIM + u] + bhh0[2 * H_DIM + u],
                                bih0[3 * H_DIM + u] + bhh0[3 * H_DIM + u]);
        s->bg1[u] = make_float4(bih1[0 * H_DIM + u] + bhh1[0 * H_DIM + u],
                                bih1[1 * H_DIM + u] + bhh1[1 * H_DIM + u],
                                bih1[2 * H_DIM + u] + bhh1[2 * H_DIM + u],
                                bih1[3 * H_DIM + u] + bhh1[3 * H_DIM + u]);
    }
    __syncthreads();

    const int warp = tid >> 5;
    const int lane = tid & 31;
    const int i8 = lane & 7;          // lane within group: owns units i8+8*uu
    const int g4 = lane >> 3;         // group 0..3 = sequence within warp
    const int wglobal = blockIdx.x * WARPS_PER_BLOCK + warp;
    const int seq_base = wglobal * SEQ_PER_WARP;
    if (seq_base >= batch) return;    // whole warp out (batch % 4 == 0)
    const int b = seq_base + g4;

    const float* xb = x + (size_t)b * T_LEN * IN_DIM;

    float h0[4] = {0.f, 0.f, 0.f, 0.f};
    float c0[4] = {0.f, 0.f, 0.f, 0.f};
    float h1[4] = {0.f, 0.f, 0.f, 0.f};
    float c1[4] = {0.f, 0.f, 0.f, 0.f};

    // x regs: lane i8 holds x[2*i8], x[2*i8+1] of its group's sequence.
    float2 xv = *reinterpret_cast<const float2*>(xb + 2 * i8);

    for (int t = 0; t < T_LEN; t++) {
        float2 xn = make_float2(0.f, 0.f);
        if (t + 1 < T_LEN)
            xn = *reinterpret_cast<const float2*>(xb + (t + 1) * IN_DIM + 2 * i8);

        // ================= Layer 0 =================
        u64 a0[4][2];
#pragma unroll
        for (int uu = 0; uu < 4; uu++) {
            ulonglong2 bb = *reinterpret_cast<const ulonglong2*>(&s->bg0[i8 + 8 * uu]);
            a0[uu][0] = bb.x;
            a0[uu][1] = bb.y;
        }
#pragma unroll
        for (int k = 0; k < IN_DIM; k++) {
            float xk = __shfl_sync(FULLMASK, (k & 1) ? xv.y : xv.x, k >> 1, 8);
            u64 xk2 = pack2(xk);
#pragma unroll
            for (int uu = 0; uu < 4; uu++) {
                ulonglong2 w = *reinterpret_cast<const ulonglong2*>(&s->wih0[k][i8 + 8 * uu]);
                a0[uu][0] = fma2(w.x, xk2, a0[uu][0]);
                a0[uu][1] = fma2(w.y, xk2, a0[uu][1]);
            }
        }
#pragma unroll
        for (int j = 0; j < H_DIM; j++) {
            float hj = __shfl_sync(FULLMASK, h0[j >> 3], j & 7, 8);
            u64 hj2 = pack2(hj);
#pragma unroll
            for (int uu = 0; uu < 4; uu++) {
                ulonglong2 w = *reinterpret_cast<const ulonglong2*>(&s->whh0[j][i8 + 8 * uu]);
                a0[uu][0] = fma2(w.x, hj2, a0[uu][0]);
                a0[uu][1] = fma2(w.y, hj2, a0[uu][1]);
            }
        }
        float h0n[4];
#pragma unroll
        for (int uu = 0; uu < 4; uu++)
            lstm_cell(a0[uu][0], a0[uu][1], h0n[uu], c0[uu]);

        // ================= Layer 1 =================
        u64 a1[4][2];
#pragma unroll
        for (int uu = 0; uu < 4; uu++) {
            ulonglong2 bb = *reinterpret_cast<const ulonglong2*>(&s->bg1[i8 + 8 * uu]);
            a1[uu][0] = bb.x;
            a1[uu][1] = bb.y;
        }
#pragma unroll
        for (int j = 0; j < H_DIM; j++) {
            float hj = __shfl_sync(FULLMASK, h0n[j >> 3], j & 7, 8);
            u64 hj2 = pack2(hj);
#pragma unroll
            for (int uu = 0; uu < 4; uu++) {
                ulonglong2 w = *reinterpret_cast<const ulonglong2*>(&s->wih1[j][i8 + 8 * uu]);
                a1[uu][0] = fma2(w.x, hj2, a1[uu][0]);
                a1[uu][1] = fma2(w.y, hj2, a1[uu][1]);
            }
        }
#pragma unroll
        for (int j = 0; j < H_DIM; j++) {
            float hj = __shfl_sync(FULLMASK, h1[j >> 3], j & 7, 8);
            u64 hj2 = pack2(hj);
#pragma unroll
            for (int uu = 0; uu < 4; uu++) {
                ulonglong2 w = *reinterpret_cast<const ulonglong2*>(&s->whh1[j][i8 + 8 * uu]);
                a1[uu][0] = fma2(w.x, hj2, a1[uu][0]);
                a1[uu][1] = fma2(w.y, hj2, a1[uu][1]);
            }
        }
#pragma unroll
        for (int uu = 0; uu < 4; uu++) {
            lstm_cell(a1[uu][0], a1[uu][1], h1[uu], c1[uu]);
            h0[uu] = h0n[uu];
        }

        xv = xn;
    }

    // ---- Head: z = relu(h1 @ W1.T + b1); y = z @ W2.T + b2 ----
    // Each lane computes outputs m = i8 and m = i8+8 for its group's sequence.
    float z0 = __ldg(b1 + i8);
    float z1 = __ldg(b1 + i8 + 8);
#pragma unroll
    for (int j = 0; j < H_DIM; j++) {
        float hj = __shfl_sync(FULLMASK, h1[j >> 3], j & 7, 8);
        z0 = fmaf(__ldg(W1 + i8 * H_DIM + j), hj, z0);
        z1 = fmaf(__ldg(W1 + (i8 + 8) * H_DIM + j), hj, z1);
    }
    z0 = fmaxf(z0, 0.f);
    z1 = fmaxf(z1, 0.f);
    float val = z0 * __ldg(W2 + i8) + z1 * __ldg(W2 + i8 + 8);
#pragma unroll
    for (int off = 4; off >= 1; off >>= 1)
        val += __shfl_xor_sync(FULLMASK, val, off, 8);
    if (i8 == 0) out[b] = val + __ldg(b2);
}

extern "C" void kernel_launch(void* const* d_in, const int* in_sizes, int n_in,
                              void* d_out, int out_size) {
    const float* x    = (const float*)d_in[0];
    const float* Wih0 = (const float*)d_in[1];
    const float* Whh0 = (const float*)d_in[2];
    const float* bih0 = (const float*)d_in[3];
    const float* bhh0 = (const float*)d_in[4];
    const float* Wih1 = (const float*)d_in[5];
    const float* Whh1 = (const float*)d_in[6];
    const float* bih1 = (const float*)d_in[7];
    const float* bhh1 = (const float*)d_in[8];
    const float* W1   = (const float*)d_in[9];
    const float* b1   = (const float*)d_in[10];
    const float* W2   = (const float*)d_in[11];
    const float* b2   = (const float*)d_in[12];
    float* out = (float*)d_out;

    int batch = in_sizes[0] / (T_LEN * IN_DIM);  // 4096

    cudaFuncSetAttribute(lstm_fused_kernel,
                         cudaFuncAttributeMaxDynamicSharedMemorySize,
                         (int)sizeof(SmemW));

    int warps_needed = (batch + SEQ_PER_WARP - 1) / SEQ_PER_WARP;  // 1024
    int blocks = (warps_needed + WARPS_PER_BLOCK - 1) / WARPS_PER_BLOCK;  // 147
    lstm_fused_kernel<<<blocks, THREADS, sizeof(SmemW)>>>(
        x, Wih0, Whh0, bih0, bhh0, Wih1, Whh1, bih1, bhh1,
        W1, b1, W2, b2, out, batch);
}